// round 12
// baseline (speedup 1.0000x reference)
#include <cuda_runtime.h>
#include <cuda_fp16.h>
#include <math.h>

#define N_SVC_ 100000
#define N_NODE_ 50000
#define FIN 16
#define HD0 128   // HEADS*HID
#define NH 4
#define OUTD 32
#define E_SS_ 800000
#define E_SN_ 400000
#define E_NS_ 400000
#define E_NN_ 400000

// ---------------- static device scratch ----------------
__device__ int g_row_ss[N_SVC_ + 1], g_row_ns[N_SVC_ + 1];
__device__ int g_row_sn[N_NODE_ + 1], g_row_nn[N_NODE_ + 1];
__device__ int g_cur_ss[N_SVC_], g_cur_ns[N_SVC_];
__device__ int g_cur_sn[N_NODE_], g_cur_nn[N_NODE_];
__device__ int g_csr_ss[E_SS_], g_csr_sn[E_SN_], g_csr_ns[E_NS_], g_csr_nn[E_NN_];
__device__ int g_bsumA[4][256];

// layer-0 features (fp16 for gather bandwidth)
__device__ __align__(16) __half g_hs0s[2][N_SVC_ * HD0];   // r0(ss), r1(sn)
__device__ __align__(16) __half g_hs0n[2][N_NODE_ * HD0];  // r2(ns), r3(nn)
__device__ __align__(16) float g_as0s[2][N_SVC_ * NH];
__device__ __align__(16) float g_as0n[2][N_NODE_ * NH];
__device__ __align__(16) float g_ad0s[2][N_SVC_ * NH];
__device__ __align__(16) float g_ad0n[2][N_NODE_ * NH];
__device__ __align__(16) float g_hS[N_SVC_ * HD0];
__device__ __align__(16) float g_hN[N_NODE_ * HD0];
// layer-1 features (fp32)
__device__ __align__(16) float g_hs1s[2][N_SVC_ * OUTD];
__device__ __align__(16) float g_hs1n[2][N_NODE_ * OUTD];
__device__ float g_as1s[2][N_SVC_];
__device__ float g_as1n[2][N_NODE_];
__device__ float g_ad1s[2][N_SVC_];
__device__ float g_ad1n[2][N_NODE_];
__device__ __align__(16) float g_wdv0[4][FIN * NH];
__device__ __align__(16) float g_wdv1[4][HD0];
__device__ double g_pool[2 * OUTD];

struct RelDesc {
    const int* src; const int* dst;
    int E, Nd;
    int* row; int* cur; int* csr; int* bsum;
};
struct Rel4 { RelDesc r[4]; };

// ---------------- wdv precompute + pool zero ----------------
__global__ void k_wdv_all(const float* __restrict__ Wd0, const float* __restrict__ ad0,
                          const float* __restrict__ Wd1, const float* __restrict__ ad1) {
    int t = threadIdx.x;  // 256
    {
        int r = t >> 6, f = (t >> 2) & 15, h = t & 3;
        float s = 0.f;
        for (int c = 0; c < 32; c++)
            s += Wd0[r * FIN * HD0 + f * HD0 + h * 32 + c] * ad0[r * HD0 + h * 32 + c];
        g_wdv0[r][f * NH + h] = s;
    }
    for (int i = t; i < 4 * HD0; i += 256) {
        int r = i >> 7, f = i & 127;
        float s = 0.f;
        for (int c = 0; c < OUTD; c++)
            s += Wd1[r * HD0 * OUTD + f * OUTD + c] * ad1[r * OUTD + c];
        g_wdv1[r][f] = s;
    }
    if (t < 2 * OUTD) g_pool[t] = 0.0;
}

// ---------------- CSR build ----------------
__global__ void k_zero_deg(Rel4 R) {
    const RelDesc rd = R.r[blockIdx.y];
    int i = blockIdx.x * 256 + threadIdx.x;
    if (i < rd.Nd) rd.cur[i] = 0;
}
__global__ void k_hist(Rel4 R) {
    const RelDesc rd = R.r[blockIdx.y];
    int e = blockIdx.x * 256 + threadIdx.x;
    if (e < rd.E) atomicAdd(&rd.cur[rd.dst[e]], 1);
}
__global__ void k_bsum(Rel4 R) {
    const RelDesc rd = R.r[blockIdx.y];
    if ((int)blockIdx.x * 512 >= rd.Nd) return;
    __shared__ int sh[512];
    int t = threadIdx.x, i = blockIdx.x * 512 + t;
    sh[t] = (i < rd.Nd) ? rd.cur[i] : 0;
    __syncthreads();
    for (int o = 256; o > 0; o >>= 1) {
        if (t < o) sh[t] += sh[t + o];
        __syncthreads();
    }
    if (t == 0) rd.bsum[blockIdx.x] = sh[0];
}
__global__ void k_bscan(Rel4 R) {
    const RelDesc rd = R.r[blockIdx.x];
    int nb = (rd.Nd + 511) >> 9;
    __shared__ int sh[256];
    int t = threadIdx.x;
    int v = (t < nb) ? rd.bsum[t] : 0;
    sh[t] = v;
    __syncthreads();
    for (int o = 1; o < 256; o <<= 1) {
        int a = (t >= o) ? sh[t - o] : 0;
        __syncthreads();
        sh[t] += a;
        __syncthreads();
    }
    if (t < nb) rd.bsum[t] = sh[t] - v;
    if (t == 255) rd.row[rd.Nd] = sh[255];
}
__global__ void k_rowptr(Rel4 R) {
    const RelDesc rd = R.r[blockIdx.y];
    if ((int)blockIdx.x * 512 >= rd.Nd) return;
    __shared__ int sh[512];
    int t = threadIdx.x, i = blockIdx.x * 512 + t;
    int v = (i < rd.Nd) ? rd.cur[i] : 0;
    sh[t] = v;
    __syncthreads();
    for (int o = 1; o < 512; o <<= 1) {
        int a = (t >= o) ? sh[t - o] : 0;
        __syncthreads();
        sh[t] += a;
        __syncthreads();
    }
    if (i < rd.Nd) {
        int rp = rd.bsum[blockIdx.x] + sh[t] - v;
        rd.row[i] = rp;
        rd.cur[i] = rp;
    }
}
__global__ void k_scatter(Rel4 R) {
    const RelDesc rd = R.r[blockIdx.y];
    int e = blockIdx.x * 256 + threadIdx.x;
    if (e < rd.E) {
        int pos = atomicAdd(&rd.cur[rd.dst[e]], 1);
        rd.csr[pos] = rd.src[e];
    }
}

// ---------------- layer-0 fused dense ----------------
struct Feat0Job {
    const float* x; int N;
    const float* Wa; const float* Wb; const float* atta; const float* attb;
    const float* wdvA; const float* wdvB;
    __half* hsa; __half* hsb;
    float* asra; float* asrb; float* adA; float* adB;
};
__global__ void k_feat0(Feat0Job j0, Feat0Job j1, int blocks0) {
    Feat0Job jb = (blockIdx.x < (unsigned)blocks0) ? j0 : j1;
    int bx = (blockIdx.x < (unsigned)blocks0) ? blockIdx.x : blockIdx.x - blocks0;
    __shared__ float sWa[FIN * HD0], sWb[FIN * HD0], sa[HD0], sb[HD0];
    __shared__ float swA[FIN * NH], swB[FIN * NH], sx[32 * FIN];
    int tid = threadIdx.x;  // 128
    for (int i = tid; i < FIN * HD0; i += 128) { sWa[i] = jb.Wa[i]; sWb[i] = jb.Wb[i]; }
    sa[tid] = jb.atta[tid]; sb[tid] = jb.attb[tid];
    if (tid < 64) { swA[tid] = jb.wdvA[tid]; swB[tid] = jb.wdvB[tid]; }
    int n0 = bx * 32;
    for (int i = tid; i < 32 * FIN; i += 128) {
        int nn = n0 + (i >> 4);
        sx[i] = (nn < jb.N) ? jb.x[nn * FIN + (i & 15)] : 0.f;
    }
    __syncthreads();
    int head = tid >> 5, lane = tid & 31;
    for (int jj = 0; jj < 32; jj++) {
        int n = n0 + jj;
        if (n >= jb.N) break;
        float va = 0.f, vb = 0.f;
#pragma unroll
        for (int f = 0; f < FIN; f++) {
            float xv = sx[jj * FIN + f];
            va += xv * sWa[f * HD0 + tid];
            vb += xv * sWb[f * HD0 + tid];
        }
        jb.hsa[(size_t)n * HD0 + tid] = __float2half_rn(va);
        jb.hsb[(size_t)n * HD0 + tid] = __float2half_rn(vb);
        float pa = va * sa[tid], pb = vb * sb[tid];
#pragma unroll
        for (int o = 16; o > 0; o >>= 1) {
            pa += __shfl_xor_sync(~0u, pa, o);
            pb += __shfl_xor_sync(~0u, pb, o);
        }
        if (lane == 0) { jb.asra[n * NH + head] = pa; jb.asrb[n * NH + head] = pb; }
    }
    for (int i = tid; i < 256; i += 128) {
        int jj = i >> 3, h = (i >> 1) & 3, r = i & 1;
        int n = n0 + jj;
        if (n < jb.N) {
            const float* w = r ? swB : swA;
            float s = 0.f;
#pragma unroll
            for (int f = 0; f < FIN; f++) s += sx[jj * FIN + f] * w[f * NH + h];
            (r ? jb.adB : jb.adA)[n * NH + h] = s;
        }
    }
}

// ---------------- layer-0 aggregation: warp/dst (R7 body, unchanged) ----------------
struct Agg0Job {
    const int* rowA; const int* csrA; const float* asA; const float* adA;
    const __half* hsA; const float* bA;
    const int* rowB; const int* csrB; const float* asB; const float* adB;
    const __half* hsB; const float* bB;
    float* hout; int Nd;
};
__device__ __forceinline__ float4 agg0_rel(const int* __restrict__ row, const int* __restrict__ csr,
                                           const float* __restrict__ asr, const float* __restrict__ adt,
                                           const __half* __restrict__ hs, int d, int lane, int h) {
    float adv = adt[d * NH + h];
    int i0 = row[d], i1 = row[d + 1];
    float4 acc = make_float4(0.f, 0.f, 0.f, 0.f);
    float den = 0.f;
    const uint2* hrow = (const uint2*)hs;
    for (int i = i0; i < i1; i++) {
        int s = csr[i];
        float e = asr[s * NH + h] + adv;
        e = e > 0.f ? e : 0.2f * e;
        float w = __expf(e);
        den += w;
        uint2 raw = hrow[(size_t)s * 32 + lane];
        float2 f0 = __half22float2(*reinterpret_cast<const __half2*>(&raw.x));
        float2 f1 = __half22float2(*reinterpret_cast<const __half2*>(&raw.y));
        acc.x += w * f0.x; acc.y += w * f0.y; acc.z += w * f1.x; acc.w += w * f1.y;
    }
    float inv = 1.f / (den + 1e-16f);
    return make_float4(acc.x * inv, acc.y * inv, acc.z * inv, acc.w * inv);
}
__global__ void k_agg0(Agg0Job j0, Agg0Job j1, int blocks0) {
    Agg0Job jb = (blockIdx.x < (unsigned)blocks0) ? j0 : j1;
    int bx = (blockIdx.x < (unsigned)blocks0) ? blockIdx.x : blockIdx.x - blocks0;
    int d = bx * 8 + (threadIdx.x >> 5);
    if (d >= jb.Nd) return;
    int lane = threadIdx.x & 31, h = lane >> 3;
    float4 rA = agg0_rel(jb.rowA, jb.csrA, jb.asA, jb.adA, jb.hsA, d, lane, h);
    float4 rB = agg0_rel(jb.rowB, jb.csrB, jb.asB, jb.adB, jb.hsB, d, lane, h);
    float4 ba = ((const float4*)jb.bA)[lane], bb = ((const float4*)jb.bB)[lane];
    float4 o;
    o.x = 0.5f * (rA.x + rB.x + ba.x + bb.x);
    o.y = 0.5f * (rA.y + rB.y + ba.y + bb.y);
    o.z = 0.5f * (rA.z + rB.z + ba.z + bb.z);
    o.w = 0.5f * (rA.w + rB.w + ba.w + bb.w);
    o.x = o.x > 0.f ? o.x : expm1f(o.x);
    o.y = o.y > 0.f ? o.y : expm1f(o.y);
    o.z = o.z > 0.f ? o.z : expm1f(o.z);
    o.w = o.w > 0.f ? o.w : expm1f(o.w);
    ((float4*)jb.hout)[(size_t)d * 32 + lane] = o;
}

// ---------------- layer-1 fused dense: transposed weights, lane-owns-channel ----------------
struct Feat1Job {
    const float* h; int N;
    const float* Wa; const float* Wb; const float* atta; const float* attb;
    const float* wdvA; const float* wdvB;
    float* h1a; float* h1b; float* asa; float* asb; float* adA; float* adB;
};
#define WPITCH 132
__global__ void k_feat1(Feat1Job j0, Feat1Job j1, int blocks0) {
    Feat1Job jb = (blockIdx.x < (unsigned)blocks0) ? j0 : j1;
    int bx = (blockIdx.x < (unsigned)blocks0) ? blockIdx.x : blockIdx.x - blocks0;
    __shared__ float sWaT[OUTD * WPITCH], sWbT[OUTD * WPITCH];
    __shared__ float sa[OUTD], sb[OUTD], swA[HD0], swB[HD0];
    int tid = threadIdx.x;  // 256
    for (int i = tid; i < HD0 * OUTD; i += 256) {
        int f = i >> 5, o = i & 31;
        sWaT[o * WPITCH + f] = jb.Wa[i];
        sWbT[o * WPITCH + f] = jb.Wb[i];
    }
    if (tid < OUTD) { sa[tid] = jb.atta[tid]; sb[tid] = jb.attb[tid]; }
    if (tid >= 128 && tid < 256) { swA[tid - 128] = jb.wdvA[tid - 128]; swB[tid - 128] = jb.wdvB[tid - 128]; }
    __syncthreads();
    int warp = tid >> 5, lane = tid & 31;
    const float4* wa = (const float4*)(sWaT + lane * WPITCH);
    const float4* wb = (const float4*)(sWbT + lane * WPITCH);
    float4 a4 = ((const float4*)swA)[lane];
    float4 b4 = ((const float4*)swB)[lane];
    for (int t = 0; t < 4; t++) {
        int n = bx * 32 + warp * 4 + t;
        if (n >= jb.N) break;
        const float4* xr = (const float4*)(jb.h + (size_t)n * HD0);
        float4 xlane = xr[lane];
        float va = 0.f, vb = 0.f;
#pragma unroll
        for (int f4 = 0; f4 < 32; f4++) {
            float4 xv = xr[f4];
            float4 A = wa[f4], B = wb[f4];
            va += xv.x * A.x + xv.y * A.y + xv.z * A.z + xv.w * A.w;
            vb += xv.x * B.x + xv.y * B.y + xv.z * B.z + xv.w * B.w;
        }
        jb.h1a[(size_t)n * OUTD + lane] = va;
        jb.h1b[(size_t)n * OUTD + lane] = vb;
        float pa = va * sa[lane], pb = vb * sb[lane];
        float da = xlane.x * a4.x + xlane.y * a4.y + xlane.z * a4.z + xlane.w * a4.w;
        float db = xlane.x * b4.x + xlane.y * b4.y + xlane.z * b4.z + xlane.w * b4.w;
#pragma unroll
        for (int o = 16; o > 0; o >>= 1) {
            pa += __shfl_xor_sync(~0u, pa, o);
            pb += __shfl_xor_sync(~0u, pb, o);
            da += __shfl_xor_sync(~0u, da, o);
            db += __shfl_xor_sync(~0u, db, o);
        }
        if (lane == 0) { jb.asa[n] = pa; jb.asb[n] = pb; jb.adA[n] = da; jb.adB[n] = db; }
    }
}

// ---------------- layer-1 aggregation (R7 body, unchanged) + fused mean-pool ----------------
struct Agg1Job {
    const int* rowA; const int* csrA; const float* asA; const float* adA;
    const float* h1A; const float* bA;
    const int* rowB; const int* csrB; const float* asB; const float* adB;
    const float* h1B; const float* bB;
    double* pool; int Nd;
};
__device__ __forceinline__ float agg1_rel(const int* __restrict__ row, const int* __restrict__ csr,
                                          const float* __restrict__ asr, const float* __restrict__ adt,
                                          const float* __restrict__ h1, int d, int lane) {
    float adv = adt[d];
    int i0 = row[d], i1 = row[d + 1];
    float acc = 0.f, den = 0.f;
    for (int i = i0; i < i1; i++) {
        int s = csr[i];
        float e = asr[s] + adv;
        e = e > 0.f ? e : 0.2f * e;
        float w = __expf(e);
        den += w;
        acc += w * h1[(size_t)s * OUTD + lane];
    }
    return acc / (den + 1e-16f);
}
__global__ void k_agg1(Agg1Job j0, Agg1Job j1, int blocks0) {
    Agg1Job jb = (blockIdx.x < (unsigned)blocks0) ? j0 : j1;
    int bx = (blockIdx.x < (unsigned)blocks0) ? blockIdx.x : blockIdx.x - blocks0;
    __shared__ double sp[8][33];
    int warp = threadIdx.x >> 5, lane = threadIdx.x & 31;
    int d = bx * 8 + warp;
    float res = 0.f;
    if (d < jb.Nd) {
        float rA = agg1_rel(jb.rowA, jb.csrA, jb.asA, jb.adA, jb.h1A, d, lane);
        float rB = agg1_rel(jb.rowB, jb.csrB, jb.asB, jb.adB, jb.h1B, d, lane);
        res = 0.5f * (rA + rB + jb.bA[lane] + jb.bB[lane]);
    }
    sp[warp][lane] = (double)res;
    __syncthreads();
    if (warp == 0) {
        double t = sp[0][lane];
#pragma unroll
        for (int k = 1; k < 8; k++) t += sp[k][lane];
        asm volatile("red.global.add.f64 [%0], %1;" :: "l"(&jb.pool[lane]), "d"(t) : "memory");
    }
}

__global__ void k_out(float* __restrict__ out) {
    int t = threadIdx.x;  // 64
    double cnt = (t < OUTD) ? (double)N_SVC_ : (double)N_NODE_;
    out[t] = (float)(g_pool[t] / cnt);
}

// ---------------- host driver ----------------
extern "C" void kernel_launch(void* const* d_in, const int* in_sizes, int n_in,
                              void* d_out, int out_size) {
    const float* x_svc = (const float*)d_in[0];
    const float* x_node = (const float*)d_in[1];
    const int* ss_s = (const int*)d_in[2]; const int* ss_d = (const int*)d_in[3];
    const int* sn_s = (const int*)d_in[4]; const int* sn_d = (const int*)d_in[5];
    const int* ns_s = (const int*)d_in[6]; const int* ns_d = (const int*)d_in[7];
    const int* nn_s = (const int*)d_in[8]; const int* nn_d = (const int*)d_in[9];
    const float* Ws0 = (const float*)d_in[10];
    const float* Wd0 = (const float*)d_in[11];
    const float* as0 = (const float*)d_in[12];
    const float* ad0 = (const float*)d_in[13];
    const float* b0  = (const float*)d_in[14];
    const float* Ws1 = (const float*)d_in[15];
    const float* Wd1 = (const float*)d_in[16];
    const float* as1 = (const float*)d_in[17];
    const float* ad1 = (const float*)d_in[18];
    const float* b1  = (const float*)d_in[19];
    int E_ss = in_sizes[2], E_sn = in_sizes[4], E_ns = in_sizes[6], E_nn = in_sizes[8];

    int *row_ss, *row_sn, *row_ns, *row_nn, *cur_ss, *cur_sn, *cur_ns, *cur_nn;
    int *csr_ss, *csr_sn, *csr_ns, *csr_nn, *bsumA;
    __half *hs0s, *hs0n;
    float *as0s, *as0n, *ad0s, *ad0n, *hS, *hN;
    float *hs1s, *hs1n, *as1s, *as1n, *ad1s, *ad1n, *wdv0, *wdv1;
    double* pool;
    cudaGetSymbolAddress((void**)&row_ss, g_row_ss);
    cudaGetSymbolAddress((void**)&row_sn, g_row_sn);
    cudaGetSymbolAddress((void**)&row_ns, g_row_ns);
    cudaGetSymbolAddress((void**)&row_nn, g_row_nn);
    cudaGetSymbolAddress((void**)&cur_ss, g_cur_ss);
    cudaGetSymbolAddress((void**)&cur_sn, g_cur_sn);
    cudaGetSymbolAddress((void**)&cur_ns, g_cur_ns);
    cudaGetSymbolAddress((void**)&cur_nn, g_cur_nn);
    cudaGetSymbolAddress((void**)&csr_ss, g_csr_ss);
    cudaGetSymbolAddress((void**)&csr_sn, g_csr_sn);
    cudaGetSymbolAddress((void**)&csr_ns, g_csr_ns);
    cudaGetSymbolAddress((void**)&csr_nn, g_csr_nn);
    cudaGetSymbolAddress((void**)&bsumA, g_bsumA);
    cudaGetSymbolAddress((void**)&hs0s, g_hs0s);
    cudaGetSymbolAddress((void**)&hs0n, g_hs0n);
    cudaGetSymbolAddress((void**)&as0s, g_as0s);
    cudaGetSymbolAddress((void**)&as0n, g_as0n);
    cudaGetSymbolAddress((void**)&ad0s, g_ad0s);
    cudaGetSymbolAddress((void**)&ad0n, g_ad0n);
    cudaGetSymbolAddress((void**)&hS, g_hS);
    cudaGetSymbolAddress((void**)&hN, g_hN);
    cudaGetSymbolAddress((void**)&hs1s, g_hs1s);
    cudaGetSymbolAddress((void**)&hs1n, g_hs1n);
    cudaGetSymbolAddress((void**)&as1s, g_as1s);
    cudaGetSymbolAddress((void**)&as1n, g_as1n);
    cudaGetSymbolAddress((void**)&ad1s, g_ad1s);
    cudaGetSymbolAddress((void**)&ad1n, g_ad1n);
    cudaGetSymbolAddress((void**)&wdv0, g_wdv0);
    cudaGetSymbolAddress((void**)&wdv1, g_wdv1);
    cudaGetSymbolAddress((void**)&pool, g_pool);

    Rel4 R;
    R.r[0] = {ss_s, ss_d, E_ss, N_SVC_,  row_ss, cur_ss, csr_ss, bsumA + 0 * 256};
    R.r[1] = {sn_s, sn_d, E_sn, N_NODE_, row_sn, cur_sn, csr_sn, bsumA + 1 * 256};
    R.r[2] = {ns_s, ns_d, E_ns, N_SVC_,  row_ns, cur_ns, csr_ns, bsumA + 2 * 256};
    R.r[3] = {nn_s, nn_d, E_nn, N_NODE_, row_nn, cur_nn, csr_nn, bsumA + 3 * 256};

    int maxE = E_ss > E_sn ? E_ss : E_sn;
    if (E_ns > maxE) maxE = E_ns;
    if (E_nn > maxE) maxE = E_nn;

    k_wdv_all<<<1, 256>>>(Wd0, ad0, Wd1, ad1);
    k_zero_deg<<<dim3((N_SVC_ + 255) / 256, 4), 256>>>(R);
    k_hist<<<dim3((maxE + 255) / 256, 4), 256>>>(R);
    k_bsum<<<dim3((N_SVC_ + 511) / 512, 4), 512>>>(R);
    k_bscan<<<4, 256>>>(R);
    k_rowptr<<<dim3((N_SVC_ + 511) / 512, 4), 512>>>(R);
    k_scatter<<<dim3((maxE + 255) / 256, 4), 256>>>(R);

    // ---- layer 0 ----
    size_t SZS = (size_t)N_SVC_ * HD0, SZN = (size_t)N_NODE_ * HD0;
    {
        Feat0Job f0, f1;
        f0 = {x_svc, N_SVC_, Ws0 + 0 * FIN * HD0, Ws0 + 1 * FIN * HD0,
              as0 + 0 * HD0, as0 + 1 * HD0, wdv0 + 0 * 64, wdv0 + 2 * 64,
              hs0s, hs0s + SZS, as0s, as0s + N_SVC_ * NH, ad0s, ad0s + N_SVC_ * NH};
        f1 = {x_node, N_NODE_, Ws0 + 2 * FIN * HD0, Ws0 + 3 * FIN * HD0,
              as0 + 2 * HD0, as0 + 3 * HD0, wdv0 + 1 * 64, wdv0 + 3 * 64,
              hs0n, hs0n + SZN, as0n, as0n + N_NODE_ * NH, ad0n, ad0n + N_NODE_ * NH};
        int b0n = (N_SVC_ + 31) / 32;
        k_feat0<<<b0n + (N_NODE_ + 31) / 32, 128>>>(f0, f1, b0n);
    }
    {
        Agg0Job a0, a1;
        a0 = {row_ss, csr_ss, as0s, ad0s, hs0s, b0 + 0 * HD0,
              row_ns, csr_ns, as0n, ad0s + N_SVC_ * NH, hs0n, b0 + 2 * HD0,
              hS, N_SVC_};
        a1 = {row_sn, csr_sn, as0s + N_SVC_ * NH, ad0n, hs0s + SZS, b0 + 1 * HD0,
              row_nn, csr_nn, as0n + N_NODE_ * NH, ad0n + N_NODE_ * NH, hs0n + SZN, b0 + 3 * HD0,
              hN, N_NODE_};
        int b0n = (N_SVC_ + 7) / 8;
        k_agg0<<<b0n + (N_NODE_ + 7) / 8, 256>>>(a0, a1, b0n);
    }

    // ---- layer 1 ----
    size_t S1S = (size_t)N_SVC_ * OUTD, S1N = (size_t)N_NODE_ * OUTD;
    {
        Feat1Job f0, f1;
        f0 = {hS, N_SVC_, Ws1 + 0 * HD0 * OUTD, Ws1 + 1 * HD0 * OUTD,
              as1 + 0 * OUTD, as1 + 1 * OUTD, wdv1 + 0 * HD0, wdv1 + 2 * HD0,
              hs1s, hs1s + S1S, as1s, as1s + N_SVC_, ad1s, ad1s + N_SVC_};
        f1 = {hN, N_NODE_, Ws1 + 2 * HD0 * OUTD, Ws1 + 3 * HD0 * OUTD,
              as1 + 2 * OUTD, as1 + 3 * OUTD, wdv1 + 1 * HD0, wdv1 + 3 * HD0,
              hs1n, hs1n + S1N, as1n, as1n + N_NODE_, ad1n, ad1n + N_NODE_};
        int b0n = (N_SVC_ + 31) / 32;
        k_feat1<<<b0n + (N_NODE_ + 31) / 32, 256>>>(f0, f1, b0n);
    }
    {
        Agg1Job a0, a1;
        a0 = {row_ss, csr_ss, as1s, ad1s, hs1s, b1 + 0 * OUTD,
              row_ns, csr_ns, as1n, ad1s + N_SVC_, hs1n, b1 + 2 * OUTD,
              pool, N_SVC_};
        a1 = {row_sn, csr_sn, as1s + N_SVC_, ad1n, hs1s + S1S, b1 + 1 * OUTD,
              row_nn, csr_nn, as1n + N_NODE_, ad1n + N_NODE_, hs1n + S1N, b1 + 3 * OUTD,
              pool + OUTD, N_NODE_};
        int b0n = (N_SVC_ + 7) / 8;
        k_agg1<<<b0n + (N_NODE_ + 7) / 8, 256>>>(a0, a1, b0n);
    }
    k_out<<<1, 64>>>((float*)d_out);
}

// round 13
// speedup vs baseline: 1.0746x; 1.0746x over previous
#include <cuda_runtime.h>
#include <cuda_fp16.h>
#include <math.h>

#define N_SVC_ 100000
#define N_NODE_ 50000
#define FIN 16
#define HD0 128   // HEADS*HID
#define NH 4
#define OUTD 32
#define E_SS_ 800000
#define E_SN_ 400000
#define E_NS_ 400000
#define E_NN_ 400000

// ---------------- static device scratch ----------------
__device__ int g_row_ss[N_SVC_ + 1], g_row_ns[N_SVC_ + 1];
__device__ int g_row_sn[N_NODE_ + 1], g_row_nn[N_NODE_ + 1];
__device__ int g_cur_ss[N_SVC_], g_cur_ns[N_SVC_];
__device__ int g_cur_sn[N_NODE_], g_cur_nn[N_NODE_];
__device__ int g_csr_ss[E_SS_], g_csr_sn[E_SN_], g_csr_ns[E_NS_], g_csr_nn[E_NN_];
__device__ int g_bsumA[4][256];

// layer-0 features (fp16 for gather bandwidth)
__device__ __align__(16) __half g_hs0s[2][N_SVC_ * HD0];   // r0(ss), r1(sn)
__device__ __align__(16) __half g_hs0n[2][N_NODE_ * HD0];  // r2(ns), r3(nn)
__device__ __align__(16) float g_as0s[2][N_SVC_ * NH];
__device__ __align__(16) float g_as0n[2][N_NODE_ * NH];
__device__ __align__(16) float g_ad0s[2][N_SVC_ * NH];
__device__ __align__(16) float g_ad0n[2][N_NODE_ * NH];
__device__ __align__(16) float g_hS[N_SVC_ * HD0];
__device__ __align__(16) float g_hN[N_NODE_ * HD0];
// layer-1 features (fp32)
__device__ __align__(16) float g_hs1s[2][N_SVC_ * OUTD];
__device__ __align__(16) float g_hs1n[2][N_NODE_ * OUTD];
__device__ float g_as1s[2][N_SVC_];
__device__ float g_as1n[2][N_NODE_];
__device__ float g_ad1s[2][N_SVC_];
__device__ float g_ad1n[2][N_NODE_];
__device__ __align__(16) float g_wdv0[4][FIN * NH];
__device__ __align__(16) float g_wdv1[4][HD0];
__device__ double g_pool[2 * OUTD];

struct RelDesc {
    const int* src; const int* dst;
    int E, Nd;
    int* row; int* cur; int* csr; int* bsum;
};
struct Rel4 { RelDesc r[4]; };

// ---------------- wdv precompute + pool zero ----------------
__global__ void k_wdv_all(const float* __restrict__ Wd0, const float* __restrict__ ad0,
                          const float* __restrict__ Wd1, const float* __restrict__ ad1) {
    int t = threadIdx.x;  // 256
    {
        int r = t >> 6, f = (t >> 2) & 15, h = t & 3;
        float s = 0.f;
        for (int c = 0; c < 32; c++)
            s += Wd0[r * FIN * HD0 + f * HD0 + h * 32 + c] * ad0[r * HD0 + h * 32 + c];
        g_wdv0[r][f * NH + h] = s;
    }
    for (int i = t; i < 4 * HD0; i += 256) {
        int r = i >> 7, f = i & 127;
        float s = 0.f;
        for (int c = 0; c < OUTD; c++)
            s += Wd1[r * HD0 * OUTD + f * OUTD + c] * ad1[r * OUTD + c];
        g_wdv1[r][f] = s;
    }
    if (t < 2 * OUTD) g_pool[t] = 0.0;
}

// ---------------- CSR build ----------------
__global__ void k_zero_deg(Rel4 R) {
    const RelDesc rd = R.r[blockIdx.y];
    int i = blockIdx.x * 256 + threadIdx.x;
    if (i < rd.Nd) rd.cur[i] = 0;
}
__global__ void k_hist(Rel4 R) {
    const RelDesc rd = R.r[blockIdx.y];
    int e = blockIdx.x * 256 + threadIdx.x;
    if (e < rd.E) atomicAdd(&rd.cur[rd.dst[e]], 1);
}
__global__ void k_bsum(Rel4 R) {
    const RelDesc rd = R.r[blockIdx.y];
    if ((int)blockIdx.x * 512 >= rd.Nd) return;
    __shared__ int sh[512];
    int t = threadIdx.x, i = blockIdx.x * 512 + t;
    sh[t] = (i < rd.Nd) ? rd.cur[i] : 0;
    __syncthreads();
    for (int o = 256; o > 0; o >>= 1) {
        if (t < o) sh[t] += sh[t + o];
        __syncthreads();
    }
    if (t == 0) rd.bsum[blockIdx.x] = sh[0];
}
__global__ void k_bscan(Rel4 R) {
    const RelDesc rd = R.r[blockIdx.x];
    int nb = (rd.Nd + 511) >> 9;
    __shared__ int sh[256];
    int t = threadIdx.x;
    int v = (t < nb) ? rd.bsum[t] : 0;
    sh[t] = v;
    __syncthreads();
    for (int o = 1; o < 256; o <<= 1) {
        int a = (t >= o) ? sh[t - o] : 0;
        __syncthreads();
        sh[t] += a;
        __syncthreads();
    }
    if (t < nb) rd.bsum[t] = sh[t] - v;
    if (t == 255) rd.row[rd.Nd] = sh[255];
}
__global__ void k_rowptr(Rel4 R) {
    const RelDesc rd = R.r[blockIdx.y];
    if ((int)blockIdx.x * 512 >= rd.Nd) return;
    __shared__ int sh[512];
    int t = threadIdx.x, i = blockIdx.x * 512 + t;
    int v = (i < rd.Nd) ? rd.cur[i] : 0;
    sh[t] = v;
    __syncthreads();
    for (int o = 1; o < 512; o <<= 1) {
        int a = (t >= o) ? sh[t - o] : 0;
        __syncthreads();
        sh[t] += a;
        __syncthreads();
    }
    if (i < rd.Nd) {
        int rp = rd.bsum[blockIdx.x] + sh[t] - v;
        rd.row[i] = rp;
        rd.cur[i] = rp;
    }
}
__global__ void k_scatter(Rel4 R) {
    const RelDesc rd = R.r[blockIdx.y];
    int e = blockIdx.x * 256 + threadIdx.x;
    if (e < rd.E) {
        int pos = atomicAdd(&rd.cur[rd.dst[e]], 1);
        rd.csr[pos] = rd.src[e];
    }
}

// ---------------- layer-0 fused dense ----------------
struct Feat0Job {
    const float* x; int N;
    const float* Wa; const float* Wb; const float* atta; const float* attb;
    const float* wdvA; const float* wdvB;
    __half* hsa; __half* hsb;
    float* asra; float* asrb; float* adA; float* adB;
};
__global__ void k_feat0(Feat0Job j0, Feat0Job j1, int blocks0) {
    Feat0Job jb = (blockIdx.x < (unsigned)blocks0) ? j0 : j1;
    int bx = (blockIdx.x < (unsigned)blocks0) ? blockIdx.x : blockIdx.x - blocks0;
    __shared__ float sWa[FIN * HD0], sWb[FIN * HD0], sa[HD0], sb[HD0];
    __shared__ float swA[FIN * NH], swB[FIN * NH], sx[32 * FIN];
    int tid = threadIdx.x;  // 128
    for (int i = tid; i < FIN * HD0; i += 128) { sWa[i] = jb.Wa[i]; sWb[i] = jb.Wb[i]; }
    sa[tid] = jb.atta[tid]; sb[tid] = jb.attb[tid];
    if (tid < 64) { swA[tid] = jb.wdvA[tid]; swB[tid] = jb.wdvB[tid]; }
    int n0 = bx * 32;
    for (int i = tid; i < 32 * FIN; i += 128) {
        int nn = n0 + (i >> 4);
        sx[i] = (nn < jb.N) ? jb.x[nn * FIN + (i & 15)] : 0.f;
    }
    __syncthreads();
    int head = tid >> 5, lane = tid & 31;
    for (int jj = 0; jj < 32; jj++) {
        int n = n0 + jj;
        if (n >= jb.N) break;
        float va = 0.f, vb = 0.f;
#pragma unroll
        for (int f = 0; f < FIN; f++) {
            float xv = sx[jj * FIN + f];
            va += xv * sWa[f * HD0 + tid];
            vb += xv * sWb[f * HD0 + tid];
        }
        jb.hsa[(size_t)n * HD0 + tid] = __float2half_rn(va);
        jb.hsb[(size_t)n * HD0 + tid] = __float2half_rn(vb);
        float pa = va * sa[tid], pb = vb * sb[tid];
#pragma unroll
        for (int o = 16; o > 0; o >>= 1) {
            pa += __shfl_xor_sync(~0u, pa, o);
            pb += __shfl_xor_sync(~0u, pb, o);
        }
        if (lane == 0) { jb.asra[n * NH + head] = pa; jb.asrb[n * NH + head] = pb; }
    }
    for (int i = tid; i < 256; i += 128) {
        int jj = i >> 3, h = (i >> 1) & 3, r = i & 1;
        int n = n0 + jj;
        if (n < jb.N) {
            const float* w = r ? swB : swA;
            float s = 0.f;
#pragma unroll
            for (int f = 0; f < FIN; f++) s += sx[jj * FIN + f] * w[f * NH + h];
            (r ? jb.adB : jb.adA)[n * NH + h] = s;
        }
    }
}

// ---------------- layer-0 aggregation: warp/dst ----------------
struct Agg0Job {
    const int* rowA; const int* csrA; const float* asA; const float* adA;
    const __half* hsA; const float* bA;
    const int* rowB; const int* csrB; const float* asB; const float* adB;
    const __half* hsB; const float* bB;
    float* hout; int Nd;
};
__device__ __forceinline__ float4 agg0_rel(const int* __restrict__ row, const int* __restrict__ csr,
                                           const float* __restrict__ asr, const float* __restrict__ adt,
                                           const __half* __restrict__ hs, int d, int lane, int h) {
    float adv = adt[d * NH + h];
    int i0 = row[d], i1 = row[d + 1];
    float4 acc = make_float4(0.f, 0.f, 0.f, 0.f);
    float den = 0.f;
    const uint2* hrow = (const uint2*)hs;
    for (int i = i0; i < i1; i++) {
        int s = csr[i];
        float e = asr[s * NH + h] + adv;
        e = e > 0.f ? e : 0.2f * e;
        float w = __expf(e);
        den += w;
        uint2 raw = hrow[(size_t)s * 32 + lane];
        float2 f0 = __half22float2(*reinterpret_cast<const __half2*>(&raw.x));
        float2 f1 = __half22float2(*reinterpret_cast<const __half2*>(&raw.y));
        acc.x += w * f0.x; acc.y += w * f0.y; acc.z += w * f1.x; acc.w += w * f1.y;
    }
    float inv = 1.f / (den + 1e-16f);
    return make_float4(acc.x * inv, acc.y * inv, acc.z * inv, acc.w * inv);
}
__global__ void k_agg0(Agg0Job j0, Agg0Job j1, int blocks0) {
    Agg0Job jb = (blockIdx.x < (unsigned)blocks0) ? j0 : j1;
    int bx = (blockIdx.x < (unsigned)blocks0) ? blockIdx.x : blockIdx.x - blocks0;
    int d = bx * 8 + (threadIdx.x >> 5);
    if (d >= jb.Nd) return;
    int lane = threadIdx.x & 31, h = lane >> 3;
    float4 rA = agg0_rel(jb.rowA, jb.csrA, jb.asA, jb.adA, jb.hsA, d, lane, h);
    float4 rB = agg0_rel(jb.rowB, jb.csrB, jb.asB, jb.adB, jb.hsB, d, lane, h);
    float4 ba = ((const float4*)jb.bA)[lane], bb = ((const float4*)jb.bB)[lane];
    float4 o;
    o.x = 0.5f * (rA.x + rB.x + ba.x + bb.x);
    o.y = 0.5f * (rA.y + rB.y + ba.y + bb.y);
    o.z = 0.5f * (rA.z + rB.z + ba.z + bb.z);
    o.w = 0.5f * (rA.w + rB.w + ba.w + bb.w);
    o.x = o.x > 0.f ? o.x : expm1f(o.x);
    o.y = o.y > 0.f ? o.y : expm1f(o.y);
    o.z = o.z > 0.f ? o.z : expm1f(o.z);
    o.w = o.w > 0.f ? o.w : expm1f(o.w);
    ((float4*)jb.hout)[(size_t)d * 32 + lane] = o;
}

// ---------------- layer-1 fused dense ----------------
struct Feat1Job {
    const float* h; int N;
    const float* Wa; const float* Wb; const float* atta; const float* attb;
    const float* wdvA; const float* wdvB;
    float* h1a; float* h1b; float* asa; float* asb; float* adA; float* adB;
};
__global__ void k_feat1(Feat1Job j0, Feat1Job j1, int blocks0) {
    Feat1Job jb = (blockIdx.x < (unsigned)blocks0) ? j0 : j1;
    int bx = (blockIdx.x < (unsigned)blocks0) ? blockIdx.x : blockIdx.x - blocks0;
    __shared__ float sWa[HD0 * OUTD], sWb[HD0 * OUTD];
    __shared__ float sa[OUTD], sb[OUTD], swA[HD0], swB[HD0];
    int tid = threadIdx.x;  // 256
    for (int i = tid; i < HD0 * OUTD; i += 256) { sWa[i] = jb.Wa[i]; sWb[i] = jb.Wb[i]; }
    if (tid < OUTD) { sa[tid] = jb.atta[tid]; sb[tid] = jb.attb[tid]; }
    if (tid >= 64 && tid < 64 + HD0) { swA[tid - 64] = jb.wdvA[tid - 64]; swB[tid - 64] = jb.wdvB[tid - 64]; }
    __syncthreads();
    int warp = tid >> 5, lane = tid & 31;
    for (int t = 0; t < 4; t++) {
        int n = bx * 32 + warp * 4 + t;
        if (n >= jb.N) break;
        float4 hv = ((const float4*)jb.h)[(size_t)n * 32 + lane];
        float va = 0.f, vb = 0.f;
#pragma unroll
        for (int f = 0; f < HD0; f++) {
            float hf = __shfl_sync(~0u, ((const float*)&hv)[f & 3], f >> 2);
            va += hf * sWa[f * OUTD + lane];
            vb += hf * sWb[f * OUTD + lane];
        }
        jb.h1a[(size_t)n * OUTD + lane] = va;
        jb.h1b[(size_t)n * OUTD + lane] = vb;
        float pa = va * sa[lane], pb = vb * sb[lane];
        float4 wA = ((const float4*)swA)[lane], wB = ((const float4*)swB)[lane];
        float da = hv.x * wA.x + hv.y * wA.y + hv.z * wA.z + hv.w * wA.w;
        float db = hv.x * wB.x + hv.y * wB.y + hv.z * wB.z + hv.w * wB.w;
#pragma unroll
        for (int o = 16; o > 0; o >>= 1) {
            pa += __shfl_xor_sync(~0u, pa, o);
            pb += __shfl_xor_sync(~0u, pb, o);
            da += __shfl_xor_sync(~0u, da, o);
            db += __shfl_xor_sync(~0u, db, o);
        }
        if (lane == 0) { jb.asa[n] = pa; jb.asb[n] = pb; jb.adA[n] = da; jb.adB[n] = db; }
    }
}

// ---------------- layer-1 aggregation + fused mean-pool ----------------
struct Agg1Job {
    const int* rowA; const int* csrA; const float* asA; const float* adA;
    const float* h1A; const float* bA;
    const int* rowB; const int* csrB; const float* asB; const float* adB;
    const float* h1B; const float* bB;
    double* pool; int Nd;
};
__device__ __forceinline__ float agg1_rel(const int* __restrict__ row, const int* __restrict__ csr,
                                          const float* __restrict__ asr, const float* __restrict__ adt,
                                          const float* __restrict__ h1, int d, int lane) {
    float adv = adt[d];
    int i0 = row[d], i1 = row[d + 1];
    float acc = 0.f, den = 0.f;
    for (int i = i0; i < i1; i++) {
        int s = csr[i];
        float e = asr[s] + adv;
        e = e > 0.f ? e : 0.2f * e;
        float w = __expf(e);
        den += w;
        acc += w * h1[(size_t)s * OUTD + lane];
    }
    return acc / (den + 1e-16f);
}
__global__ void k_agg1(Agg1Job j0, Agg1Job j1, int blocks0) {
    Agg1Job jb = (blockIdx.x < (unsigned)blocks0) ? j0 : j1;
    int bx = (blockIdx.x < (unsigned)blocks0) ? blockIdx.x : blockIdx.x - blocks0;
    __shared__ double sp[8][33];
    int warp = threadIdx.x >> 5, lane = threadIdx.x & 31;
    int d = bx * 8 + warp;
    float res = 0.f;
    if (d < jb.Nd) {
        float rA = agg1_rel(jb.rowA, jb.csrA, jb.asA, jb.adA, jb.h1A, d, lane);
        float rB = agg1_rel(jb.rowB, jb.csrB, jb.asB, jb.adB, jb.h1B, d, lane);
        res = 0.5f * (rA + rB + jb.bA[lane] + jb.bB[lane]);
    }
    sp[warp][lane] = (double)res;
    __syncthreads();
    if (warp == 0) {
        double t = sp[0][lane];
#pragma unroll
        for (int k = 1; k < 8; k++) t += sp[k][lane];
        asm volatile("red.global.add.f64 [%0], %1;" :: "l"(&jb.pool[lane]), "d"(t) : "memory");
    }
}

__global__ void k_out(float* __restrict__ out) {
    int t = threadIdx.x;  // 64
    double cnt = (t < OUTD) ? (double)N_SVC_ : (double)N_NODE_;
    out[t] = (float)(g_pool[t] / cnt);
}

// ---------------- host driver (fork/join: CSR build overlaps wdv+feat0) ----------------
extern "C" void kernel_launch(void* const* d_in, const int* in_sizes, int n_in,
                              void* d_out, int out_size) {
    const float* x_svc = (const float*)d_in[0];
    const float* x_node = (const float*)d_in[1];
    const int* ss_s = (const int*)d_in[2]; const int* ss_d = (const int*)d_in[3];
    const int* sn_s = (const int*)d_in[4]; const int* sn_d = (const int*)d_in[5];
    const int* ns_s = (const int*)d_in[6]; const int* ns_d = (const int*)d_in[7];
    const int* nn_s = (const int*)d_in[8]; const int* nn_d = (const int*)d_in[9];
    const float* Ws0 = (const float*)d_in[10];
    const float* Wd0 = (const float*)d_in[11];
    const float* as0 = (const float*)d_in[12];
    const float* ad0 = (const float*)d_in[13];
    const float* b0  = (const float*)d_in[14];
    const float* Ws1 = (const float*)d_in[15];
    const float* Wd1 = (const float*)d_in[16];
    const float* as1 = (const float*)d_in[17];
    const float* ad1 = (const float*)d_in[18];
    const float* b1  = (const float*)d_in[19];
    int E_ss = in_sizes[2], E_sn = in_sizes[4], E_ns = in_sizes[6], E_nn = in_sizes[8];

    int *row_ss, *row_sn, *row_ns, *row_nn, *cur_ss, *cur_sn, *cur_ns, *cur_nn;
    int *csr_ss, *csr_sn, *csr_ns, *csr_nn, *bsumA;
    __half *hs0s, *hs0n;
    float *as0s, *as0n, *ad0s, *ad0n, *hS, *hN;
    float *hs1s, *hs1n, *as1s, *as1n, *ad1s, *ad1n, *wdv0, *wdv1;
    double* pool;
    cudaGetSymbolAddress((void**)&row_ss, g_row_ss);
    cudaGetSymbolAddress((void**)&row_sn, g_row_sn);
    cudaGetSymbolAddress((void**)&row_ns, g_row_ns);
    cudaGetSymbolAddress((void**)&row_nn, g_row_nn);
    cudaGetSymbolAddress((void**)&cur_ss, g_cur_ss);
    cudaGetSymbolAddress((void**)&cur_sn, g_cur_sn);
    cudaGetSymbolAddress((void**)&cur_ns, g_cur_ns);
    cudaGetSymbolAddress((void**)&cur_nn, g_cur_nn);
    cudaGetSymbolAddress((void**)&csr_ss, g_csr_ss);
    cudaGetSymbolAddress((void**)&csr_sn, g_csr_sn);
    cudaGetSymbolAddress((void**)&csr_ns, g_csr_ns);
    cudaGetSymbolAddress((void**)&csr_nn, g_csr_nn);
    cudaGetSymbolAddress((void**)&bsumA, g_bsumA);
    cudaGetSymbolAddress((void**)&hs0s, g_hs0s);
    cudaGetSymbolAddress((void**)&hs0n, g_hs0n);
    cudaGetSymbolAddress((void**)&as0s, g_as0s);
    cudaGetSymbolAddress((void**)&as0n, g_as0n);
    cudaGetSymbolAddress((void**)&ad0s, g_ad0s);
    cudaGetSymbolAddress((void**)&ad0n, g_ad0n);
    cudaGetSymbolAddress((void**)&hS, g_hS);
    cudaGetSymbolAddress((void**)&hN, g_hN);
    cudaGetSymbolAddress((void**)&hs1s, g_hs1s);
    cudaGetSymbolAddress((void**)&hs1n, g_hs1n);
    cudaGetSymbolAddress((void**)&as1s, g_as1s);
    cudaGetSymbolAddress((void**)&as1n, g_as1n);
    cudaGetSymbolAddress((void**)&ad1s, g_ad1s);
    cudaGetSymbolAddress((void**)&ad1n, g_ad1n);
    cudaGetSymbolAddress((void**)&wdv0, g_wdv0);
    cudaGetSymbolAddress((void**)&wdv1, g_wdv1);
    cudaGetSymbolAddress((void**)&pool, g_pool);

    Rel4 R;
    R.r[0] = {ss_s, ss_d, E_ss, N_SVC_,  row_ss, cur_ss, csr_ss, bsumA + 0 * 256};
    R.r[1] = {sn_s, sn_d, E_sn, N_NODE_, row_sn, cur_sn, csr_sn, bsumA + 1 * 256};
    R.r[2] = {ns_s, ns_d, E_ns, N_SVC_,  row_ns, cur_ns, csr_ns, bsumA + 2 * 256};
    R.r[3] = {nn_s, nn_d, E_nn, N_SVC_ > N_NODE_ ? N_NODE_ : N_NODE_, row_nn, cur_nn, csr_nn, bsumA + 3 * 256};
    R.r[3].Nd = N_NODE_;

    int maxE = E_ss > E_sn ? E_ss : E_sn;
    if (E_ns > maxE) maxE = E_ns;
    if (E_nn > maxE) maxE = E_nn;

    // fork: CSR build on side stream, dense chain on main (legacy) stream
    cudaStream_t s2;
    cudaEvent_t evFork, evJoin;
    cudaStreamCreateWithFlags(&s2, cudaStreamNonBlocking);
    cudaEventCreateWithFlags(&evFork, cudaEventDisableTiming);
    cudaEventCreateWithFlags(&evJoin, cudaEventDisableTiming);

    cudaEventRecord(evFork, 0);
    cudaStreamWaitEvent(s2, evFork, 0);

    // --- side stream: CSR build ---
    k_zero_deg<<<dim3((N_SVC_ + 255) / 256, 4), 256, 0, s2>>>(R);
    k_hist<<<dim3((maxE + 255) / 256, 4), 256, 0, s2>>>(R);
    k_bsum<<<dim3((N_SVC_ + 511) / 512, 4), 512, 0, s2>>>(R);
    k_bscan<<<4, 256, 0, s2>>>(R);
    k_rowptr<<<dim3((N_SVC_ + 511) / 512, 4), 512, 0, s2>>>(R);
    k_scatter<<<dim3((maxE + 255) / 256, 4), 256, 0, s2>>>(R);
    cudaEventRecord(evJoin, s2);

    // --- main stream: dense layer 0 ---
    k_wdv_all<<<1, 256>>>(Wd0, ad0, Wd1, ad1);
    size_t SZS = (size_t)N_SVC_ * HD0, SZN = (size_t)N_NODE_ * HD0;
    {
        Feat0Job f0, f1;
        f0 = {x_svc, N_SVC_, Ws0 + 0 * FIN * HD0, Ws0 + 1 * FIN * HD0,
              as0 + 0 * HD0, as0 + 1 * HD0, wdv0 + 0 * 64, wdv0 + 2 * 64,
              hs0s, hs0s + SZS, as0s, as0s + N_SVC_ * NH, ad0s, ad0s + N_SVC_ * NH};
        f1 = {x_node, N_NODE_, Ws0 + 2 * FIN * HD0, Ws0 + 3 * FIN * HD0,
              as0 + 2 * HD0, as0 + 3 * HD0, wdv0 + 1 * 64, wdv0 + 3 * 64,
              hs0n, hs0n + SZN, as0n, as0n + N_NODE_ * NH, ad0n, ad0n + N_NODE_ * NH};
        int b0n = (N_SVC_ + 31) / 32;
        k_feat0<<<b0n + (N_NODE_ + 31) / 32, 128>>>(f0, f1, b0n);
    }

    // join: agg0 needs both CSR and feat0
    cudaStreamWaitEvent(0, evJoin, 0);
    {
        Agg0Job a0, a1;
        a0 = {row_ss, csr_ss, as0s, ad0s, hs0s, b0 + 0 * HD0,
              row_ns, csr_ns, as0n, ad0s + N_SVC_ * NH, hs0n, b0 + 2 * HD0,
              hS, N_SVC_};
        a1 = {row_sn, csr_sn, as0s + N_SVC_ * NH, ad0n, hs0s + SZS, b0 + 1 * HD0,
              row_nn, csr_nn, as0n + N_NODE_ * NH, ad0n + N_NODE_ * NH, hs0n + SZN, b0 + 3 * HD0,
              hN, N_NODE_};
        int b0n = (N_SVC_ + 7) / 8;
        k_agg0<<<b0n + (N_NODE_ + 7) / 8, 256>>>(a0, a1, b0n);
    }

    // ---- layer 1 ----
    size_t S1S = (size_t)N_SVC_ * OUTD, S1N = (size_t)N_NODE_ * OUTD;
    {
        Feat1Job f0, f1;
        f0 = {hS, N_SVC_, Ws1 + 0 * HD0 * OUTD, Ws1 + 1 * HD0 * OUTD,
              as1 + 0 * OUTD, as1 + 1 * OUTD, wdv1 + 0 * HD0, wdv1 + 2 * HD0,
              hs1s, hs1s + S1S, as1s, as1s + N_SVC_, ad1s, ad1s + N_SVC_};
        f1 = {hN, N_NODE_, Ws1 + 2 * HD0 * OUTD, Ws1 + 3 * HD0 * OUTD,
              as1 + 2 * OUTD, as1 + 3 * OUTD, wdv1 + 1 * HD0, wdv1 + 3 * HD0,
              hs1n, hs1n + S1N, as1n, as1n + N_NODE_, ad1n, ad1n + N_NODE_};
        int b0n = (N_SVC_ + 31) / 32;
        k_feat1<<<b0n + (N_NODE_ + 31) / 32, 256>>>(f0, f1, b0n);
    }
    {
        Agg1Job a0, a1;
        a0 = {row_ss, csr_ss, as1s, ad1s, hs1s, b1 + 0 * OUTD,
              row_ns, csr_ns, as1n, ad1s + N_SVC_, hs1n, b1 + 2 * OUTD,
              pool, N_SVC_};
        a1 = {row_sn, csr_sn, as1s + N_SVC_, ad1n, hs1s + S1S, b1 + 1 * OUTD,
              row_nn, csr_nn, as1n + N_NODE_, ad1n + N_NODE_, hs1n + S1N, b1 + 3 * OUTD,
              pool + OUTD, N_NODE_};
        int b0n = (N_SVC_ + 7) / 8;
        k_agg1<<<b0n + (N_NODE_ + 7) / 8, 256>>>(a0, a1, b0n);
    }
    k_out<<<1, 64>>>((float*)d_out);
    // Note: s2/evFork/evJoin intentionally not destroyed here — destroying a
    // forked stream/event mid-capture is illegal; kernel_launch is called only
    // a handful of times, so the host-side handle leak is bounded and benign.
}